// round 14
// baseline (speedup 1.0000x reference)
#include <cuda_runtime.h>
#include <cuda_bf16.h>
#include <cstdint>

#define TSTEPS 2048
#define BATCH  32
#define IDIM   512
#define HDIM   512
#define GDIM   2048   // 4*H

#define RG      128
#define P1T     4      // timesteps per p1 CTA

#define TOTX (TSTEPS * BATCH * IDIM)
#define TOTW (GDIM * IDIM)

// rec smem layout (words)
#define SLABWORDS (2 * 8 * 36)          // per warp: H plane + L plane, [8][36]
#define SREDOFF   (8 * SLABWORDS)       // 4608
#define SREDQ     160                   // per (w,q): 16 j * 10
#define RECSMEM   ((SREDOFF + 2 * 8 * 4 * SREDQ) * 4)   // 59392 B

// ---- static device scratch ----
__device__ float g_xpre[(size_t)TSTEPS * GDIM * BATCH];     // [t][g][b]
__device__ unsigned g_hhi[2][BATCH * 256];                  // h hi plane [b][kpair]
__device__ unsigned g_hlo[2][BATCH * 256];                  // h lo plane
// per-producer-CTA counters: (jb, bb) -> own 128B line
__device__ __align__(128) unsigned long long g_cntP[32 * 4 * 16];
__device__ uint4 g_xhi4[TOTX / 8], g_xlo4[TOTX / 8];
__device__ uint4 g_whi4[TOTW / 8], g_wlo4[TOTW / 8];

// ---- helpers ----
__device__ __forceinline__ void mma_bf16(float (&d)[4], const unsigned (&a)[4],
                                         unsigned b0, unsigned b1)
{
    asm("mma.sync.aligned.m16n8k16.row.col.f32.bf16.bf16.f32 "
        "{%0,%1,%2,%3}, {%4,%5,%6,%7}, {%8,%9}, {%0,%1,%2,%3};"
        : "+f"(d[0]), "+f"(d[1]), "+f"(d[2]), "+f"(d[3])
        : "r"(a[0]), "r"(a[1]), "r"(a[2]), "r"(a[3]), "r"(b0), "r"(b1));
}
__device__ __forceinline__ void cpasync16(uint32_t s, const void* g)
{
    asm volatile("cp.async.cg.shared.global [%0], [%1], 16;"
                 :: "r"(s), "l"(g) : "memory");
}
__device__ __forceinline__ void bsplit(float f0, float f1,
                                       unsigned& hp, unsigned& lp)
{
    asm("cvt.rn.bf16x2.f32 %0, %1, %2;" : "=r"(hp) : "f"(f1), "f"(f0));
    float h0 = __uint_as_float(hp << 16);
    float h1 = __uint_as_float(hp & 0xFFFF0000u);
    float r0 = f0 - h0, r1 = f1 - h1;
    asm("cvt.rn.bf16x2.f32 %0, %1, %2;" : "=r"(lp) : "f"(r1), "f"(r0));
}
__device__ __forceinline__ float fsig(float x)
{
    return __fdividef(1.f, 1.f + __expf(-x));
}
__device__ __forceinline__ float ftanh(float x)
{
    float ax = fabsf(x);
    float e  = __expf(-2.f * ax);
    float t  = __fdividef(1.f - e, 1.f + e);
    return copysignf(t, x);
}
__device__ __forceinline__ void gbar_arrive(unsigned long long* p)
{
    asm volatile("red.release.gpu.add.u64 [%0], %1;"
                 :: "l"(p), "l"(1ULL) : "memory");
}
__device__ __forceinline__ unsigned long long ld_acq(const unsigned long long* p)
{
    unsigned long long v;
    asm volatile("ld.acquire.gpu.b64 %0, [%1];" : "=l"(v) : "l"(p) : "memory");
    return v;
}

// ============================================================
// Prep: split fp32 -> bf16 hi/lo planes (x, Wi)
// ============================================================
__global__ void __launch_bounds__(256) split_x(const float* __restrict__ x)
{
    int i = blockIdx.x * 256 + threadIdx.x;
    __nv_bfloat16* hp = (__nv_bfloat16*)g_xhi4;
    __nv_bfloat16* lp = (__nv_bfloat16*)g_xlo4;
    float v = x[i];
    __nv_bfloat16 h = __float2bfloat16(v);
    hp[i] = h;
    lp[i] = __float2bfloat16(v - __bfloat162float(h));
}
__global__ void __launch_bounds__(256) split_wi(const float* __restrict__ W)
{
    int i = blockIdx.x * 256 + threadIdx.x;
    __nv_bfloat16* hp = (__nv_bfloat16*)g_whi4;
    __nv_bfloat16* lp = (__nv_bfloat16*)g_wlo4;
    float v = W[i];
    __nv_bfloat16 h = __float2bfloat16(v);
    hp[i] = h;
    lp[i] = __float2bfloat16(v - __bfloat162float(h));
}

// ============================================================
// Phase 1: 128 g x 128 n (4 t x 32 b) bf16 split-MMA — unchanged (R12)
// ============================================================
extern __shared__ __align__(16) unsigned dynsm[];

__global__ void __launch_bounds__(256) p1_gemm(
    const float* __restrict__ bi, const float* __restrict__ bh)
{
    unsigned* sw0 = dynsm;
    unsigned* sw1 = dynsm + 128 * 36;
    unsigned* sx0 = dynsm + 2 * 128 * 36;
    unsigned* sx1 = dynsm + 3 * 128 * 36;

    const int t0    = blockIdx.y * P1T;
    const int gbase = blockIdx.x * 128;
    const int tid   = threadIdx.x;
    const int wid   = tid >> 5;
    const int lane  = tid & 31;
    const int g     = lane >> 2;
    const int t4    = lane & 3;

    float acc[16][4];
    #pragma unroll
    for (int nt = 0; nt < 16; nt++)
        #pragma unroll
        for (int i = 0; i < 4; i++) acc[nt][i] = 0.f;

    for (int kb = 0; kb < IDIM; kb += 64) {
        __syncthreads();
        #pragma unroll
        for (int r = 0; r < 4; r++) {
            int ch  = r * 256 + tid;
            int row = ch >> 3, c8 = ch & 7;
            size_t src = ((size_t)(gbase + row) * IDIM + kb) / 8 + c8;
            ((uint4*)sw0)[row * 9 + c8] = g_whi4[src];
            ((uint4*)sw1)[row * 9 + c8] = g_wlo4[src];
        }
        #pragma unroll
        for (int r = 0; r < 4; r++) {
            int ch  = r * 256 + tid;
            int row = ch >> 3, c8 = ch & 7;
            int tl = row >> 5, b = row & 31;
            size_t src = ((size_t)(t0 + tl) * BATCH + b) * (IDIM / 8)
                         + kb / 8 + c8;
            ((uint4*)sx0)[row * 9 + c8] = g_xhi4[src];
            ((uint4*)sx1)[row * 9 + c8] = g_xlo4[src];
        }
        __syncthreads();

        #pragma unroll
        for (int c = 0; c < 4; c++) {
            const int aw = (wid * 16 + g) * 36 + c * 8 + t4;
            unsigned ahi[4], alo[4];
            ahi[0] = sw0[aw];            ahi[1] = sw0[aw + 8 * 36];
            ahi[2] = sw0[aw + 4];        ahi[3] = sw0[aw + 8 * 36 + 4];
            alo[0] = sw1[aw];            alo[1] = sw1[aw + 8 * 36];
            alo[2] = sw1[aw + 4];        alo[3] = sw1[aw + 8 * 36 + 4];
            #pragma unroll
            for (int nt = 0; nt < 16; nt++) {
                const int bw = (nt * 8 + g) * 36 + c * 8 + t4;
                unsigned bh0 = sx0[bw], bh1 = sx0[bw + 4];
                unsigned bl0 = sx1[bw], bl1 = sx1[bw + 4];
                mma_bf16(acc[nt], ahi, bh0, bh1);
                mma_bf16(acc[nt], alo, bh0, bh1);
                mma_bf16(acc[nt], ahi, bl0, bl1);
            }
        }
    }

    const int grow0 = gbase + wid * 16 + g;
    const int grow1 = grow0 + 8;
    const float bb0 = __ldg(bi + grow0) + __ldg(bh + grow0);
    const float bb1 = __ldg(bi + grow1) + __ldg(bh + grow1);
    #pragma unroll
    for (int nt = 0; nt < 16; nt++) {
        int tl = nt >> 2;
        int b  = (nt & 3) * 8 + 2 * t4;
        float* op = g_xpre + (size_t)(t0 + tl) * GDIM * BATCH;
        *(float2*)(op + (size_t)grow0 * BATCH + b) =
            make_float2(acc[nt][0] + bb0, acc[nt][1] + bb0);
        *(float2*)(op + (size_t)grow1 * BATCH + b) =
            make_float2(acc[nt][2] + bb1, acc[nt][3] + bb1);
    }
}

// ============================================================
// Phase 2 v3: warp w = k-eighth [64w,64w+64) over all 4 gates x 16 j.
// Private per-warp slab; per-producer-CTA counters (4 producers/warp);
// arrival-ordered per-chunk stage + MMA pipeline; 8-way cell reduce.
// ============================================================
__global__ void __launch_bounds__(256) lstm_rec(
    const float* __restrict__ Wh, float* __restrict__ out)
{
    const int tid  = threadIdx.x;
    const int cta  = blockIdx.x;
    const int jb   = cta >> 2;             // 0..31
    const int bb   = cta & 3;              // 0..3
    const int j0   = jb * 16;
    const int b0   = bb * 8;
    const int lane = tid & 31;
    const int gid  = lane >> 2;            // 0..7
    const int t4   = lane & 3;             // 0..3
    const int w    = tid >> 5;             // warp = k-eighth

    unsigned* sH = dynsm + w * SLABWORDS;            // [8][36]
    unsigned* sL = sH + 8 * 36;
    float* sred  = (float*)(dynsm + SREDOFF);        // [2][8][4][16][10]

    // arrive counter (own CTA), poll counters (producers of my k-eighth)
    unsigned long long* acnt = &g_cntP[(jb * 4 + bb) * 16];
    unsigned long long* pcnt = &g_cntP[(((w << 2) | (lane & 3)) * 4 + bb) * 16];
    const unsigned long long per = 4ULL * (1 + TSTEPS);
    unsigned long long pbase = 0;
    if (lane < 4) pbase = (ld_acq(pcnt) / per) * per;

    // ---- preload Wh fragments: [q gate][c chunk] bf16 hi/lo packed ----
    unsigned ahi[4][4][4], alo[4][4][4];
    #pragma unroll
    for (int q = 0; q < 4; q++) {
        const int r0 = q * HDIM + j0 + gid;
        const int r1 = r0 + 8;
        #pragma unroll
        for (int c = 0; c < 4; c++) {
            int k0 = w * 64 + c * 16 + 2 * t4;
            float a00 = Wh[(size_t)r0 * HDIM + k0];
            float a01 = Wh[(size_t)r0 * HDIM + k0 + 1];
            float a10 = Wh[(size_t)r1 * HDIM + k0];
            float a11 = Wh[(size_t)r1 * HDIM + k0 + 1];
            float a20 = Wh[(size_t)r0 * HDIM + k0 + 8];
            float a21 = Wh[(size_t)r0 * HDIM + k0 + 9];
            float a30 = Wh[(size_t)r1 * HDIM + k0 + 8];
            float a31 = Wh[(size_t)r1 * HDIM + k0 + 9];
            bsplit(a00, a01, ahi[q][c][0], alo[q][c][0]);
            bsplit(a10, a11, ahi[q][c][1], alo[q][c][1]);
            bsplit(a20, a21, ahi[q][c][2], alo[q][c][2]);
            bsplit(a30, a31, ahi[q][c][3], alo[q][c][3]);
        }
    }

    // cell ownership (tid<128): j = tid>>3, b = tid&7
    const int uj = tid >> 3;
    const int ub = tid & 7;
    const int ujeven = !(uj & 1);
    const int um = uj >> 1;
    float creg = 0.f;

    // ---- init: zero own h slice, warp-scope arrive (cell warps) ----
    if (tid < 128) {
        if (ujeven) {
            g_hhi[0][(b0 + ub) * 256 + jb * 8 + um] = 0u;
            g_hlo[0][(b0 + ub) * 256 + jb * 8 + um] = 0u;
        }
        __syncwarp();
        if (lane == 0) gbar_arrive(acnt);
    }

    // prefetch x_pre for t=0 (cell warps)
    float xq[4];
    if (tid < 128) {
        #pragma unroll
        for (int q = 0; q < 4; q++)
            xq[q] = __ldg(g_xpre + ((size_t)q * HDIM + j0 + uj) * BATCH + b0 + ub);
    }

    // staging roles (per warp, per chunk: 32 x 16B granules)
    const int srow  = lane >> 2;           // 0..7 batch row
    const int sgran = lane & 3;            // plane (bit1) + half (bit0)
    const int splane = sgran >> 1;
    const int shalf  = sgran & 1;
    uint32_t dstb = (uint32_t)__cvta_generic_to_shared(
        (splane ? sL : sH) + srow * 36 + shalf * 4);

    for (int t = 0; t < TSTEPS; t++) {
        const int p = t & 1;
        float* srp = sred + (size_t)p * (8 * 4 * SREDQ) + w * 4 * SREDQ;

        const unsigned* gsrc = (splane ? g_hlo[p] : g_hhi[p])
                               + (b0 + srow) * 256 + w * 32 + shalf * 4;
        const unsigned long long thr = pbase + 4ULL * (t + 1);

        float accA[4][4], accB[4][4], accC[4][4];
        #pragma unroll
        for (int q = 0; q < 4; q++)
            #pragma unroll
            for (int i = 0; i < 4; i++) {
                accA[q][i] = 0.f; accB[q][i] = 0.f; accC[q][i] = 0.f;
            }

        // ---- arrival-ordered per-chunk stage + MMA ----
        unsigned done = 0;
        while (done != 0xFu) {
            unsigned long long v = 0;
            if (lane < 4) v = ld_acq(pcnt);
            unsigned newr = (__ballot_sync(0xFFFFFFFFu, (lane < 4) && (v >= thr))
                             & 0xFu) & ~done;
            if (!newr) continue;

            #pragma unroll
            for (int c = 0; c < 4; c++)
                if ((newr >> c) & 1)
                    cpasync16(dstb + (uint32_t)(c * 8) * 4u, gsrc + c * 8);
            asm volatile("cp.async.commit_group;");
            asm volatile("cp.async.wait_group 0;" ::: "memory");
            __syncwarp();

            #pragma unroll
            for (int c = 0; c < 4; c++)
                if ((newr >> c) & 1) {
                    unsigned bh0 = sH[gid * 36 + c * 8 + t4];
                    unsigned bh1 = sH[gid * 36 + c * 8 + t4 + 4];
                    unsigned bl0 = sL[gid * 36 + c * 8 + t4];
                    unsigned bl1 = sL[gid * 36 + c * 8 + t4 + 4];
                    #pragma unroll
                    for (int q = 0; q < 4; q++) {
                        mma_bf16(accA[q], ahi[q][c], bh0, bh1);
                        mma_bf16(accB[q], alo[q][c], bh0, bh1);
                        mma_bf16(accC[q], ahi[q][c], bl0, bl1);
                    }
                }
            done |= newr;
        }

        // ---- spill partials: [q][j][b] ----
        #pragma unroll
        for (int q = 0; q < 4; q++) {
            float d0 = accA[q][0] + accB[q][0] + accC[q][0];
            float d1 = accA[q][1] + accB[q][1] + accC[q][1];
            float d2 = accA[q][2] + accB[q][2] + accC[q][2];
            float d3 = accA[q][3] + accB[q][3] + accC[q][3];
            *(float2*)&srp[q * SREDQ + gid * 10 + 2 * t4]       = make_float2(d0, d1);
            *(float2*)&srp[q * SREDQ + (gid + 8) * 10 + 2 * t4] = make_float2(d2, d3);
        }

        if (tid >= 128) {
            asm volatile("bar.arrive 3, 256;" ::: "memory");
            continue;
        }
        asm volatile("bar.sync 3, 256;" ::: "memory");

        // ---- cell: 8-way reduce + activations + pack + arrive ----
        {
            const float* sp = sred + (size_t)p * (8 * 4 * SREDQ);
            float pre[4];
            #pragma unroll
            for (int q = 0; q < 4; q++) {
                float s = xq[q];
                #pragma unroll
                for (int ww = 0; ww < 8; ww++)
                    s += sp[(ww * 4 + q) * SREDQ + uj * 10 + ub];
                pre[q] = s;
            }
            float ig = fsig(pre[0]);
            float fg = fsig(pre[1]);
            float og = fsig(pre[2]);
            float gt = ftanh(pre[3]);
            creg = creg * fg + ig * gt;
            float hn = og * ftanh(creg);
            float hn1 = __shfl_down_sync(0xFFFFFFFFu, hn, 8);
            if (ujeven) {
                unsigned ph, pl;
                bsplit(hn, hn1, ph, pl);
                g_hhi[p ^ 1][(b0 + ub) * 256 + jb * 8 + um] = ph;
                g_hlo[p ^ 1][(b0 + ub) * 256 + jb * 8 + um] = pl;
            }
            __syncwarp();
            if (lane == 0) gbar_arrive(acnt);      // publish h(t+1)

            // off-critical-path work after arrive
            out[((size_t)t * BATCH + b0 + ub) * HDIM + j0 + uj] = hn;
            if (t == TSTEPS - 1) {
                size_t o2 = (size_t)TSTEPS * BATCH * HDIM;
                out[o2 + (b0 + ub) * HDIM + j0 + uj] = hn;
                out[o2 + BATCH * HDIM + (b0 + ub) * HDIM + j0 + uj] = creg;
            }
            int tn = (t + 1 < TSTEPS) ? t + 1 : t;
            #pragma unroll
            for (int q = 0; q < 4; q++)
                xq[q] = __ldg(g_xpre + ((size_t)tn * GDIM + q * HDIM + j0 + uj) * BATCH + b0 + ub);
        }
    }
}

// ============================================================
extern "C" void kernel_launch(void* const* d_in, const int* in_sizes, int n_in,
                              void* d_out, int out_size)
{
    const float* x  = (const float*)d_in[0];
    const float* Wi = (const float*)d_in[1];
    const float* bi = (const float*)d_in[2];
    const float* Wh = (const float*)d_in[3];
    const float* bh = (const float*)d_in[4];
    float* out = (float*)d_out;

    size_t p1_smem = (size_t)(4 * 128 * 36) * sizeof(unsigned); // 73728 B
    cudaFuncSetAttribute(p1_gemm, cudaFuncAttributeMaxDynamicSharedMemorySize,
                         (int)p1_smem);
    cudaFuncSetAttribute(lstm_rec, cudaFuncAttributeMaxDynamicSharedMemorySize,
                         RECSMEM);

    split_x<<<TOTX / 256, 256>>>(x);
    split_wi<<<TOTW / 256, 256>>>(Wi);
    dim3 g1(GDIM / 128, TSTEPS / P1T);
    p1_gemm<<<g1, 256, p1_smem>>>(bi, bh);
    lstm_rec<<<RG, 256, RECSMEM>>>(Wh, out);
}

// round 15
// speedup vs baseline: 1.2157x; 1.2157x over previous
#include <cuda_runtime.h>
#include <cuda_bf16.h>
#include <cstdint>

#define TSTEPS 2048
#define BATCH  32
#define IDIM   512
#define HDIM   512
#define GDIM   2048   // 4*H

#define RG      128
#define CARRV   64     // arrivals per counter per barrier: 16 CTAs * 4 warps
#define SLABW   260    // slab b-row stride in words
#define NBAR    (1 + TSTEPS)

#define P1T     4      // timesteps per p1 CTA (N = 32*P1T = 128)

#define TOTX (TSTEPS * BATCH * IDIM)
#define TOTW (GDIM * IDIM)

// ---- static device scratch ----
__device__ float g_xpre[(size_t)TSTEPS * GDIM * BATCH];     // [t][g][b]
__device__ unsigned g_hhi[2][BATCH * 256];                  // h hi plane [b][kpair]
__device__ unsigned g_hlo[2][BATCH * 256];                  // h lo plane
// counters: (bb, half) -> own 128B line
__device__ __align__(128) unsigned long long g_cnt8[4 * 2 * 16];
__device__ uint4 g_xhi4[TOTX / 8], g_xlo4[TOTX / 8];
__device__ uint4 g_whi4[TOTW / 8], g_wlo4[TOTW / 8];

// ---- helpers ----
__device__ __forceinline__ void mma_bf16(float (&d)[4], const unsigned (&a)[4],
                                         unsigned b0, unsigned b1)
{
    asm("mma.sync.aligned.m16n8k16.row.col.f32.bf16.bf16.f32 "
        "{%0,%1,%2,%3}, {%4,%5,%6,%7}, {%8,%9}, {%0,%1,%2,%3};"
        : "+f"(d[0]), "+f"(d[1]), "+f"(d[2]), "+f"(d[3])
        : "r"(a[0]), "r"(a[1]), "r"(a[2]), "r"(a[3]), "r"(b0), "r"(b1));
}
__device__ __forceinline__ void cpasync16(uint32_t s, const void* g)
{
    asm volatile("cp.async.cg.shared.global [%0], [%1], 16;"
                 :: "r"(s), "l"(g) : "memory");
}
__device__ __forceinline__ void bsplit(float f0, float f1,
                                       unsigned& hp, unsigned& lp)
{
    asm("cvt.rn.bf16x2.f32 %0, %1, %2;" : "=r"(hp) : "f"(f1), "f"(f0));
    float h0 = __uint_as_float(hp << 16);
    float h1 = __uint_as_float(hp & 0xFFFF0000u);
    float r0 = f0 - h0, r1 = f1 - h1;
    asm("cvt.rn.bf16x2.f32 %0, %1, %2;" : "=r"(lp) : "f"(r1), "f"(r0));
}
__device__ __forceinline__ float fsig(float x)
{
    return __fdividef(1.f, 1.f + __expf(-x));
}
__device__ __forceinline__ float ftanh(float x)
{
    float ax = fabsf(x);
    float e  = __expf(-2.f * ax);
    float t  = __fdividef(1.f - e, 1.f + e);
    return copysignf(t, x);
}
__device__ __forceinline__ void gbar_arrive(unsigned long long* p)
{
    asm volatile("red.release.gpu.add.u64 [%0], %1;"
                 :: "l"(p), "l"(1ULL) : "memory");
}
__device__ __forceinline__ void gbar_spin(unsigned long long* p,
                                          unsigned long long target)
{
    unsigned long long v;
    do {
        asm volatile("ld.acquire.gpu.b64 %0, [%1];"
                     : "=l"(v) : "l"(p) : "memory");
    } while (v < target);
}

// ============================================================
// Prep: split fp32 -> bf16 hi/lo planes (x, Wi)
// ============================================================
__global__ void __launch_bounds__(256) split_x(const float* __restrict__ x)
{
    int i = blockIdx.x * 256 + threadIdx.x;
    __nv_bfloat16* hp = (__nv_bfloat16*)g_xhi4;
    __nv_bfloat16* lp = (__nv_bfloat16*)g_xlo4;
    float v = x[i];
    __nv_bfloat16 h = __float2bfloat16(v);
    hp[i] = h;
    lp[i] = __float2bfloat16(v - __bfloat162float(h));
}
__global__ void __launch_bounds__(256) split_wi(const float* __restrict__ W)
{
    int i = blockIdx.x * 256 + threadIdx.x;
    __nv_bfloat16* hp = (__nv_bfloat16*)g_whi4;
    __nv_bfloat16* lp = (__nv_bfloat16*)g_wlo4;
    float v = W[i];
    __nv_bfloat16 h = __float2bfloat16(v);
    hp[i] = h;
    lp[i] = __float2bfloat16(v - __bfloat162float(h));
}

// ============================================================
// Phase 1 v3: 128 g x 128 n (4 t x 32 b), K=512.
// cp.async staging (no register round-trip) + 2 CTAs/SM so one
// CTA's MMA hides the other's stage latency.
// ============================================================
extern __shared__ __align__(16) unsigned dynsm[];

__global__ void __launch_bounds__(256, 2) p1_gemm(
    const float* __restrict__ bi, const float* __restrict__ bh)
{
    unsigned* sw0 = dynsm;
    unsigned* sw1 = dynsm + 128 * 36;
    unsigned* sx0 = dynsm + 2 * 128 * 36;
    unsigned* sx1 = dynsm + 3 * 128 * 36;

    const int t0    = blockIdx.y * P1T;
    const int gbase = blockIdx.x * 128;
    const int tid   = threadIdx.x;
    const int wid   = tid >> 5;
    const int lane  = tid & 31;
    const int g     = lane >> 2;
    const int t4    = lane & 3;

    // staging roles: 4 uint4 per thread per plane; dst fixed per thread
    uint32_t wdst0[4], wdst1[4], xdst0[4], xdst1[4];
    size_t   wbase[4], xbase[4];
    {
        uint32_t b0 = (uint32_t)__cvta_generic_to_shared(sw0);
        uint32_t b1 = (uint32_t)__cvta_generic_to_shared(sw1);
        uint32_t b2 = (uint32_t)__cvta_generic_to_shared(sx0);
        uint32_t b3 = (uint32_t)__cvta_generic_to_shared(sx1);
        #pragma unroll
        for (int r = 0; r < 4; r++) {
            int ch  = r * 256 + tid;
            int row = ch >> 3, c8 = ch & 7;
            uint32_t doff = (uint32_t)(row * 9 + c8) * 16u;
            wdst0[r] = b0 + doff;  wdst1[r] = b1 + doff;
            xdst0[r] = b2 + doff;  xdst1[r] = b3 + doff;
            wbase[r] = (size_t)(gbase + row) * 64 + c8;
            int tl = row >> 5, b = row & 31;
            xbase[r] = ((size_t)(t0 + tl) * BATCH + b) * 64 + c8;
        }
    }

    float acc[16][4];
    #pragma unroll
    for (int nt = 0; nt < 16; nt++)
        #pragma unroll
        for (int i = 0; i < 4; i++) acc[nt][i] = 0.f;

    for (int kb = 0; kb < IDIM; kb += 64) {
        const int k8 = kb >> 3;
        __syncthreads();
        #pragma unroll
        for (int r = 0; r < 4; r++) {
            cpasync16(wdst0[r], g_whi4 + wbase[r] + k8);
            cpasync16(wdst1[r], g_wlo4 + wbase[r] + k8);
            cpasync16(xdst0[r], g_xhi4 + xbase[r] + k8);
            cpasync16(xdst1[r], g_xlo4 + xbase[r] + k8);
        }
        asm volatile("cp.async.commit_group;");
        asm volatile("cp.async.wait_group 0;" ::: "memory");
        __syncthreads();

        #pragma unroll
        for (int c = 0; c < 4; c++) {
            const int aw = (wid * 16 + g) * 36 + c * 8 + t4;
            unsigned ahi[4], alo[4];
            ahi[0] = sw0[aw];            ahi[1] = sw0[aw + 8 * 36];
            ahi[2] = sw0[aw + 4];        ahi[3] = sw0[aw + 8 * 36 + 4];
            alo[0] = sw1[aw];            alo[1] = sw1[aw + 8 * 36];
            alo[2] = sw1[aw + 4];        alo[3] = sw1[aw + 8 * 36 + 4];
            #pragma unroll
            for (int nt = 0; nt < 16; nt++) {
                const int bw = (nt * 8 + g) * 36 + c * 8 + t4;
                unsigned bh0 = sx0[bw], bh1 = sx0[bw + 4];
                unsigned bl0 = sx1[bw], bl1 = sx1[bw + 4];
                mma_bf16(acc[nt], ahi, bh0, bh1);
                mma_bf16(acc[nt], alo, bh0, bh1);
                mma_bf16(acc[nt], ahi, bl0, bl1);
            }
        }
    }

    const int grow0 = gbase + wid * 16 + g;
    const int grow1 = grow0 + 8;
    const float bb0 = __ldg(bi + grow0) + __ldg(bh + grow0);
    const float bb1 = __ldg(bi + grow1) + __ldg(bh + grow1);
    #pragma unroll
    for (int nt = 0; nt < 16; nt++) {
        int tl = nt >> 2;
        int b  = (nt & 3) * 8 + 2 * t4;
        float* op = g_xpre + (size_t)(t0 + tl) * GDIM * BATCH;
        *(float2*)(op + (size_t)grow0 * BATCH + b) =
            make_float2(acc[nt][0] + bb0, acc[nt][1] + bb0);
        *(float2*)(op + (size_t)grow1 * BATCH + b) =
            make_float2(acc[nt][2] + bb1, acc[nt][3] + bb1);
    }
}

// ============================================================
// Phase 2: persistent recurrence — EXACT R12 version (best: 5.03 ms).
// ============================================================
__global__ void __launch_bounds__(256) lstm_rec(
    const float* __restrict__ Wh, float* __restrict__ out)
{
    __shared__ __align__(16) unsigned slabH[8][SLABW];  // [b][kpair]
    __shared__ __align__(16) unsigned slabL[8][SLABW];
    __shared__ float sred[2][4][2][16][10];             // [parity][q][kh][j][b]

    const int tid  = threadIdx.x;
    const int cta  = blockIdx.x;
    const int jb   = cta >> 2;
    const int bb   = cta & 3;
    const int j0   = jb * 16;
    const int b0   = bb * 8;
    const int lane = tid & 31;
    const int gid  = lane >> 2;
    const int t4   = lane & 3;
    const int warp = tid >> 5;
    const int mt   = warp & 3;             // gate type
    const int kh   = warp >> 2;            // k-half of this warp-group

    const int half = jb >> 4;              // which half this CTA produces
    unsigned long long* acnt = &g_cnt8[(bb * 2 + half) * 16];  // arrive
    unsigned long long* scnt = &g_cnt8[(bb * 2 + kh) * 16];    // spin

    unsigned long long v0;
    asm volatile("ld.acquire.gpu.b64 %0, [%1];" : "=l"(v0) : "l"(scnt) : "memory");
    const unsigned long long per  = (unsigned long long)NBAR * CARRV;
    const unsigned long long base = (v0 / per) * per;

    // ---- preload Wh fragments (bf16 hi/lo packed, registers) ----
    unsigned ahi[16][4], alo[16][4];
    {
        const int r0 = mt * HDIM + j0 + gid;
        const int r1 = r0 + 8;
        #pragma unroll
        for (int c = 0; c < 16; c++) {
            int kb = kh * 256 + c * 16 + 2 * t4;
            float a00 = Wh[(size_t)r0 * HDIM + kb];
            float a01 = Wh[(size_t)r0 * HDIM + kb + 1];
            float a10 = Wh[(size_t)r1 * HDIM + kb];
            float a11 = Wh[(size_t)r1 * HDIM + kb + 1];
            float a20 = Wh[(size_t)r0 * HDIM + kb + 8];
            float a21 = Wh[(size_t)r0 * HDIM + kb + 9];
            float a30 = Wh[(size_t)r1 * HDIM + kb + 8];
            float a31 = Wh[(size_t)r1 * HDIM + kb + 9];
            bsplit(a00, a01, ahi[c][0], alo[c][0]);
            bsplit(a10, a11, ahi[c][1], alo[c][1]);
            bsplit(a20, a21, ahi[c][2], alo[c][2]);
            bsplit(a30, a31, ahi[c][3], alo[c][3]);
        }
    }

    // cell ownership (tid<128): j = tid>>3, b = tid&7
    const int uj = tid >> 3;
    const int ub = tid & 7;
    const int ujeven = !(uj & 1);
    const int um = uj >> 1;
    float creg = 0.f;

    // ---- init: zero h planes, arrive (cell warps only) ----
    if (tid < 128) {
        if (ujeven) {
            g_hhi[0][(b0 + ub) * 256 + jb * 8 + um] = 0u;
            g_hlo[0][(b0 + ub) * 256 + jb * 8 + um] = 0u;
        }
        __syncwarp();
        if (lane == 0) gbar_arrive(acnt);
    }

    // prefetch x_pre for t=0 (cell warps)
    float xq[4];
    if (tid < 128) {
        #pragma unroll
        for (int q = 0; q < 4; q++)
            xq[q] = __ldg(g_xpre + ((size_t)q * HDIM + j0 + uj) * BATCH + b0 + ub);
    }

    // staging roles (within kh group of 128 threads)
    const int gt  = tid & 127;
    const int sb  = gt >> 4;
    const int sc  = gt & 15;
    uint32_t dstH = (uint32_t)__cvta_generic_to_shared(&slabH[sb][kh * 128 + sc * 4]);
    uint32_t dstL = (uint32_t)__cvta_generic_to_shared(&slabL[sb][kh * 128 + sc * 4]);

    for (int t = 0; t < TSTEPS; t++) {
        const int p = t & 1;

        gbar_spin(scnt, base + (unsigned long long)(t + 1) * CARRV);

        // ---- stage own kh half ----
        {
            const unsigned* srcH = &g_hhi[p][(b0 + sb) * 256 + kh * 128 + sc * 4];
            const unsigned* srcL = &g_hlo[p][(b0 + sb) * 256 + kh * 128 + sc * 4];
            cpasync16(dstH,        srcH);
            cpasync16(dstH + 256u, srcH + 64);
            cpasync16(dstL,        srcL);
            cpasync16(dstL + 256u, srcL + 64);
            asm volatile("cp.async.commit_group;");
            asm volatile("cp.async.wait_group 0;" ::: "memory");
        }
        asm volatile("bar.sync %0, 128;" :: "r"(1 + kh) : "memory");

        // ---- MMA: 16 chunks x 3 passes ----
        float accA[4], accB[4], accC[4];
        #pragma unroll
        for (int i = 0; i < 4; i++) { accA[i] = 0.f; accB[i] = 0.f; accC[i] = 0.f; }

        #pragma unroll
        for (int c = 0; c < 16; c++) {
            int w = kh * 128 + c * 8 + t4;
            unsigned bh0 = slabH[gid][w];
            unsigned bh1 = slabH[gid][w + 4];
            unsigned bl0 = slabL[gid][w];
            unsigned bl1 = slabL[gid][w + 4];
            mma_bf16(accA, ahi[c], bh0, bh1);
            mma_bf16(accB, alo[c], bh0, bh1);
            mma_bf16(accC, ahi[c], bl0, bl1);
        }

        // ---- spill into parity buffer ----
        {
            float d0 = accA[0] + accB[0] + accC[0];
            float d1 = accA[1] + accB[1] + accC[1];
            float d2 = accA[2] + accB[2] + accC[2];
            float d3 = accA[3] + accB[3] + accC[3];
            *(float2*)&sred[p][mt][kh][gid][2 * t4]     = make_float2(d0, d1);
            *(float2*)&sred[p][mt][kh][gid + 8][2 * t4] = make_float2(d2, d3);
        }

        if (tid >= 128) {
            asm volatile("bar.arrive 3, 256;" ::: "memory");
            continue;
        }
        asm volatile("bar.sync 3, 256;" ::: "memory");

        // ---- cell (warps 0-3): reduce, activations, pack, arrive ----
        {
            float pre0 = xq[0] + sred[p][0][0][uj][ub] + sred[p][0][1][uj][ub];
            float pre1 = xq[1] + sred[p][1][0][uj][ub] + sred[p][1][1][uj][ub];
            float pre2 = xq[2] + sred[p][2][0][uj][ub] + sred[p][2][1][uj][ub];
            float pre3 = xq[3] + sred[p][3][0][uj][ub] + sred[p][3][1][uj][ub];
            float ig = fsig(pre0);
            float fg = fsig(pre1);
            float og = fsig(pre2);
            float gt = ftanh(pre3);
            creg = creg * fg + ig * gt;
            float hn = og * ftanh(creg);
            float hn1 = __shfl_down_sync(0xFFFFFFFFu, hn, 8);
            if (ujeven) {
                unsigned ph, pl;
                bsplit(hn, hn1, ph, pl);
                g_hhi[p ^ 1][(b0 + ub) * 256 + jb * 8 + um] = ph;
                g_hlo[p ^ 1][(b0 + ub) * 256 + jb * 8 + um] = pl;
            }
            __syncwarp();
            if (lane == 0) gbar_arrive(acnt);      // publish h(t+1)

            out[((size_t)t * BATCH + b0 + ub) * HDIM + j0 + uj] = hn;
            if (t == TSTEPS - 1) {
                size_t o2 = (size_t)TSTEPS * BATCH * HDIM;
                out[o2 + (b0 + ub) * HDIM + j0 + uj] = hn;
                out[o2 + BATCH * HDIM + (b0 + ub) * HDIM + j0 + uj] = creg;
            }
            int tn = (t + 1 < TSTEPS) ? t + 1 : t;
            #pragma unroll
            for (int q = 0; q < 4; q++)
                xq[q] = __ldg(g_xpre + ((size_t)tn * GDIM + q * HDIM + j0 + uj) * BATCH + b0 + ub);
        }
    }
}

// ============================================================
extern "C" void kernel_launch(void* const* d_in, const int* in_sizes, int n_in,
                              void* d_out, int out_size)
{
    const float* x  = (const float*)d_in[0];
    const float* Wi = (const float*)d_in[1];
    const float* bi = (const float*)d_in[2];
    const float* Wh = (const float*)d_in[3];
    const float* bh = (const float*)d_in[4];
    float* out = (float*)d_out;

    size_t p1_smem = (size_t)(4 * 128 * 36) * sizeof(unsigned); // 73728 B
    cudaFuncSetAttribute(p1_gemm, cudaFuncAttributeMaxDynamicSharedMemorySize,
                         (int)p1_smem);

    split_x<<<TOTX / 256, 256>>>(x);
    split_wi<<<TOTW / 256, 256>>>(Wi);
    dim3 g1(GDIM / 128, TSTEPS / P1T);
    p1_gemm<<<g1, 256, p1_smem>>>(bi, bh);
    lstm_rec<<<RG, 256>>>(Wh, out);
}